// round 12
// baseline (speedup 1.0000x reference)
#include <cuda_runtime.h>
#include <cuda_bf16.h>
#include <cstdint>

#define SD 512
#define NB 512
#define SCALE 0.044194173824159216f

#define LDC 132        // fp32 staging stride (floats)
#define LDE1 80        // k1 byte stride: 32-bf16 rows (BK=32)
#define LDE 144        // k2 A byte stride: 64-bf16 rows
#define LDV2 528       // k2 B byte stride: 256-bf16 rows + 16B pad
#define K1_SMEM 67584  // A0@0,A1@10240,B0@20480,B1@30720; Cs fp32 aliases
#define K2_SMEM 104448 // A bufs @0,@18432; B bufs @36864,@70656 (33792 each)

// ---- scratch (device globals; no allocation) ----
__device__ __align__(16) __nv_bfloat16 g_E[(size_t)NB * SD * SD];
__device__ __align__(16) __nv_bfloat16 g_Vh[(size_t)NB * SD * SD];
__device__ float g_partZ[NB][4][SD];
__device__ float g_Zinv[NB][SD];

__device__ __forceinline__ uint2 pack4(float4 v) {
    __nv_bfloat162 a = __float22bfloat162_rn(make_float2(v.x, v.y));
    __nv_bfloat162 b = __float22bfloat162_rn(make_float2(v.z, v.w));
    uint2 u; u.x = *(uint32_t*)&a; u.y = *(uint32_t*)&b; return u;
}
__device__ __forceinline__ uint4 pack8(float4 a, float4 b) {
    uint2 lo = pack4(a), hi = pack4(b);
    uint4 u; u.x = lo.x; u.y = lo.y; u.z = hi.x; u.w = hi.y; return u;
}
__device__ __forceinline__ uint32_t smem_u32(const void* p) {
    uint32_t a;
    asm("{ .reg .u64 t; cvta.to.shared.u64 t, %1; cvt.u32.u64 %0, t; }" : "=r"(a) : "l"(p));
    return a;
}
__device__ __forceinline__ void cpa16(uint32_t dst, const void* src) {
    asm volatile("cp.async.cg.shared.global [%0], [%1], 16;" :: "r"(dst), "l"(src));
}
#define CP_COMMIT() asm volatile("cp.async.commit_group;" ::: "memory")
#define CP_WAIT1()  asm volatile("cp.async.wait_group 1;" ::: "memory")
#define CP_WAIT0()  asm volatile("cp.async.wait_group 0;" ::: "memory")

__device__ __forceinline__ void ldsm4(uint32_t* r, uint32_t a) {
    asm volatile("ldmatrix.sync.aligned.m8n8.x4.shared.b16 {%0,%1,%2,%3}, [%4];"
                 : "=r"(r[0]), "=r"(r[1]), "=r"(r[2]), "=r"(r[3]) : "r"(a));
}
__device__ __forceinline__ void ldsm4t(uint32_t* r, uint32_t a) {
    asm volatile("ldmatrix.sync.aligned.m8n8.x4.trans.shared.b16 {%0,%1,%2,%3}, [%4];"
                 : "=r"(r[0]), "=r"(r[1]), "=r"(r[2]), "=r"(r[3]) : "r"(a));
}
__device__ __forceinline__ void mma16816(float* d, const uint32_t* a, const uint32_t* b) {
    asm volatile(
        "mma.sync.aligned.m16n8k16.row.col.f32.bf16.bf16.f32 "
        "{%0,%1,%2,%3},{%4,%5,%6,%7},{%8,%9},{%0,%1,%2,%3};"
        : "+f"(d[0]), "+f"(d[1]), "+f"(d[2]), "+f"(d[3])
        : "r"(a[0]), "r"(a[1]), "r"(a[2]), "r"(a[3]), "r"(b[0]), "r"(b[1]));
}

// ---------------------------------------------------------------------------
// k1: S = Q K^T (raw mma); register-prefetch + smem double-buffer, BK=32.
// Verbatim from R11 (best known: ~625us).
// ---------------------------------------------------------------------------
__global__ void __launch_bounds__(256, 2) k1_qk(const float* __restrict__ Q,
                                                const float* __restrict__ Km)
{
    extern __shared__ char sm[];
    const uint32_t sb = smem_u32(sm);
    __shared__ float zsh[256];

    const int batch = blockIdx.y, it = blockIdx.x >> 2, nt = blockIdx.x & 3;
    const float* Qb = Q  + ((size_t)batch * SD + it * 128) * SD;
    const float* Kb = Km + ((size_t)batch * SD + nt * 128) * SD;

    const int t = threadIdx.x, lane = t & 31, wid = t >> 5;
    const int R = (wid & 3) * 32, C = (wid >> 2) * 64;

    float d[2][8][4];
#pragma unroll
    for (int i = 0; i < 2; i++)
#pragma unroll
        for (int j = 0; j < 8; j++)
#pragma unroll
            for (int e = 0; e < 4; e++) d[i][j][e] = 0.0f;

    const int r0 = t >> 3, fc = (t & 7) * 4;
    const int aRow = (lane & 7) + ((lane >> 3) & 1) * 8;
    const uint32_t aK = ((lane >> 4) & 1) * 16;
    const uint32_t aBase = sb + (uint32_t)(R + aRow) * LDE1 + aK;
    const int bRow = (lane & 7) + ((lane >> 4) & 1) * 8;
    const uint32_t bK = ((lane >> 3) & 1) * 16;
    const uint32_t bBase = sb + 20480u + (uint32_t)(C + bRow) * LDE1 + bK;

    float4 pq[4], pk[4];

    auto ldgc = [&](int kk) {
#pragma unroll
        for (int p = 0; p < 4; p++) {
            const int row = r0 + p * 32;
            pq[p] = *(const float4*)(Qb + (size_t)row * SD + kk + fc);
            pk[p] = *(const float4*)(Kb + (size_t)row * SD + kk + fc);
        }
    };
    auto stsc = [&](int buf) {
#pragma unroll
        for (int p = 0; p < 4; p++) {
            const int row = r0 + p * 32;
            *(uint2*)(sm + buf * 10240 + row * LDE1 + fc * 2) = pack4(pq[p]);
            *(uint2*)(sm + 20480 + buf * 10240 + row * LDE1 + fc * 2) = pack4(pk[p]);
        }
    };

    ldgc(0);
    stsc(0);
    ldgc(32);
    __syncthreads();

#pragma unroll 1
    for (int c = 0; c < 16; c++) {
        const int buf = c & 1;
        const uint32_t aB = aBase + (uint32_t)buf * 10240u;
        const uint32_t bB = bBase + (uint32_t)buf * 10240u;
        uint32_t afr[2][4], bfr[4][4];
#pragma unroll
        for (int ks = 0; ks < 2; ks++) {
            const uint32_t ko = (uint32_t)ks * 32;
#pragma unroll
            for (int i = 0; i < 2; i++) ldsm4(afr[i], aB + i * 16 * LDE1 + ko);
#pragma unroll
            for (int j = 0; j < 4; j++) ldsm4(bfr[j], bB + j * 16 * LDE1 + ko);
#pragma unroll
            for (int i = 0; i < 2; i++)
#pragma unroll
                for (int j = 0; j < 4; j++) {
                    mma16816(d[i][2 * j],     afr[i], &bfr[j][0]);
                    mma16816(d[i][2 * j + 1], afr[i], &bfr[j][2]);
                }
        }
        __syncthreads();
        if (c < 15) {
            stsc(buf ^ 1);
            if (c < 14) ldgc((c + 2) * 32);
            __syncthreads();
        }
    }

#pragma unroll
    for (int i = 0; i < 2; i++)
#pragma unroll
        for (int j = 0; j < 8; j++)
#pragma unroll
            for (int e = 0; e < 4; e++)
                d[i][j][e] = __expf(d[i][j][e] * SCALE);

    float* Cs = (float*)sm;
    __syncthreads();
#pragma unroll
    for (int i = 0; i < 2; i++)
#pragma unroll
        for (int j = 0; j < 8; j++) {
            const int row = R + 16 * i + (lane >> 2);
            const int col = C + 8 * j + (lane & 3) * 2;
            *(float2*)&Cs[row * LDC + col] = make_float2(d[i][j][0], d[i][j][1]);
            *(float2*)&Cs[(row + 8) * LDC + col] = make_float2(d[i][j][2], d[i][j][3]);
        }
    __syncthreads();

    {
        const int col = t & 127, half = t >> 7;
        float zsum = 0.f;
#pragma unroll 8
        for (int r = half * 64; r < half * 64 + 64; r++)
            zsum += Cs[r * LDC + col];
        zsh[half * 128 + col] = zsum;
        __syncthreads();
        if (t < 128)
            g_partZ[batch][it][nt * 128 + t] = zsh[t] + zsh[128 + t];
    }

    __nv_bfloat16* Eb = g_E + ((size_t)batch * SD + it * 128) * SD + nt * 128;
    {
        const int row = t >> 1, c0 = (t & 1) * 64;
        const float* src = Cs + row * LDC + c0;
#pragma unroll
        for (int i = 0; i < 8; i++)
            *(uint4*)(Eb + (size_t)row * SD + c0 + i * 8) =
                pack8(*(const float4*)(src + i * 8), *(const float4*)(src + i * 8 + 4));
    }
}

// ---------------------------------------------------------------------------
__global__ void __launch_bounds__(512) k_zred()
{
    const int b = blockIdx.x, c = threadIdx.x;
    float z = g_partZ[b][0][c] + g_partZ[b][1][c] + g_partZ[b][2][c] + g_partZ[b][3][c];
    g_Zinv[b][c] = 1.0f / z;
}

// ---------------------------------------------------------------------------
__global__ void __launch_bounds__(256) kvs(const float* __restrict__ V)
{
    const int i = blockIdx.x * blockDim.x + threadIdx.x;
    const int b = i >> 15;
    const int k = (i & 32767) >> 6;
    const float zi = g_Zinv[b][k];
    const float4* src = (const float4*)(V + (size_t)i * 8);
    float4 a = src[0], c4 = src[1];
    a.x *= zi; a.y *= zi; a.z *= zi; a.w *= zi;
    c4.x *= zi; c4.y *= zi; c4.z *= zi; c4.w *= zi;
    *(uint4*)(g_Vh + (size_t)i * 8) = pack8(a, c4);
}

// ---------------------------------------------------------------------------
// k2: out = E @ V' — CTA tile 128x256, 512 threads = 16 warps (4 row x 4 col),
// warp tile 32x64, cp.async double-buffered BK=64. 2 CTAs/SM (32 warps).
// grid (8, 512): blockIdx.x = it*2 + jh.
// smem: A bufs @0,@18432 (128 x 144B); B bufs @36864,@70656 (64 x 528B).
// ---------------------------------------------------------------------------
__global__ void __launch_bounds__(512, 2) k2_pv(float* __restrict__ O)
{
    extern __shared__ char sm[];
    const uint32_t sb = smem_u32(sm);

    const int batch = blockIdx.y, it = blockIdx.x >> 1, jh = blockIdx.x & 1;
    const char* Eblk = (const char*)(g_E + ((size_t)batch * SD + it * 128) * SD);
    const char* Vblk = (const char*)(g_Vh + (size_t)batch * SD * SD + jh * 256);

    const int t = threadIdx.x, lane = t & 31, wid = t >> 5;
    const int R = (wid & 3) * 32, C = (wid >> 2) * 64;   // wc in 0..3 -> 256 cols

    // cp.async fill coords: A 1024 chunks -> 2/thread; B 2048 chunks -> 4/thread
    const int ar = t >> 2, ac = (t & 3) * 2;   // A row 0..127, chunk cols {ac, ac+1}
    const int br = t >> 3, bc = (t & 7) * 4;   // B row 0..63, chunk cols bc..bc+3

    // ldmatrix per-lane offsets
    const int aRow = (lane & 7) + ((lane >> 3) & 1) * 8;
    const uint32_t aK = ((lane >> 4) & 1) * 16;
    const uint32_t aBase = sb + (uint32_t)(R + aRow) * LDE + aK;
    const int bKrow = lane & 15;
    const uint32_t bN = ((lane >> 4) & 1) * 16;
    const uint32_t bBase = sb + 36864u + (uint32_t)bKrow * LDV2 + (uint32_t)C * 2 + bN;

    float d[2][8][4];
#pragma unroll
    for (int i = 0; i < 2; i++)
#pragma unroll
        for (int j = 0; j < 8; j++)
#pragma unroll
            for (int e = 0; e < 4; e++) d[i][j][e] = 0.0f;

#pragma unroll 1
    for (int pre = 0; pre < 2; pre++) {
        const uint32_t abuf = sb + pre * 18432;
        const uint32_t bbuf = sb + 36864 + pre * 33792;
        const int kk = pre * 64;
#pragma unroll
        for (int q = 0; q < 2; q++)
            cpa16(abuf + (uint32_t)(ar * 144 + (ac + q) * 16),
                  Eblk + (size_t)ar * 1024 + (size_t)kk * 2 + (ac + q) * 16);
#pragma unroll
        for (int q = 0; q < 4; q++)
            cpa16(bbuf + (uint32_t)(br * LDV2 + (bc + q) * 16),
                  Vblk + (size_t)(kk + br) * 1024 + (bc + q) * 16);
        CP_COMMIT();
    }

#pragma unroll 1
    for (int c = 0; c < 8; c++) {
        if (c < 6) CP_WAIT1(); else CP_WAIT0();
        __syncthreads();
        const int buf = c & 1;
        const uint32_t aB = aBase + buf * 18432u;
        const uint32_t bB = bBase + buf * 33792u;

        uint32_t afr[2][2][4], bfr[2][4][4];
#pragma unroll
        for (int i = 0; i < 2; i++) ldsm4(afr[0][i], aB + i * 16 * LDE);
#pragma unroll
        for (int j = 0; j < 4; j++) ldsm4t(bfr[0][j], bB + j * 32);

#pragma unroll
        for (int ks = 0; ks < 4; ks++) {
            const int cur = ks & 1, nxt = cur ^ 1;
            if (ks < 3) {
                const uint32_t ao = (uint32_t)(ks + 1) * 32;
                const uint32_t bo = (uint32_t)(ks + 1) * (16 * LDV2);
#pragma unroll
                for (int i = 0; i < 2; i++) ldsm4(afr[nxt][i], aB + i * 16 * LDE + ao);
#pragma unroll
                for (int j = 0; j < 4; j++) ldsm4t(bfr[nxt][j], bB + j * 32 + bo);
            }
#pragma unroll
            for (int i = 0; i < 2; i++)
#pragma unroll
                for (int j = 0; j < 4; j++) {
                    mma16816(d[i][2 * j],     afr[cur][i], &bfr[cur][j][0]);
                    mma16816(d[i][2 * j + 1], afr[cur][i], &bfr[cur][j][2]);
                }
        }
        __syncthreads();

        if (c < 6) {
            const uint32_t abuf = sb + buf * 18432;
            const uint32_t bbuf = sb + 36864 + buf * 33792;
            const int kk = (c + 2) * 64;
#pragma unroll
            for (int q = 0; q < 2; q++)
                cpa16(abuf + (uint32_t)(ar * 144 + (ac + q) * 16),
                      Eblk + (size_t)ar * 1024 + (size_t)kk * 2 + (ac + q) * 16);
#pragma unroll
            for (int q = 0; q < 4; q++)
                cpa16(bbuf + (uint32_t)(br * LDV2 + (bc + q) * 16),
                      Vblk + (size_t)(kk + br) * 1024 + (bc + q) * 16);
            CP_COMMIT();
        }
    }

    float* Ob = O + ((size_t)batch * SD + it * 128) * SD + jh * 256;
#pragma unroll
    for (int i = 0; i < 2; i++)
#pragma unroll
        for (int j = 0; j < 8; j++) {
            const int row = R + 16 * i + (lane >> 2);
            const int col = C + 8 * j + (lane & 3) * 2;
            *(float2*)(Ob + (size_t)row * SD + col) = make_float2(d[i][j][0], d[i][j][1]);
            *(float2*)(Ob + (size_t)(row + 8) * SD + col) = make_float2(d[i][j][2], d[i][j][3]);
        }
}

// ---------------------------------------------------------------------------
extern "C" void kernel_launch(void* const* d_in, const int* in_sizes, int n_in,
                              void* d_out, int out_size)
{
    (void)in_sizes; (void)n_in; (void)out_size;
    const float* Q = (const float*)d_in[1];
    const float* K = (const float*)d_in[2];
    const float* V = (const float*)d_in[3];
    float* out = (float*)d_out;

    cudaFuncSetAttribute(k1_qk, cudaFuncAttributeMaxDynamicSharedMemorySize, K1_SMEM);
    cudaFuncSetAttribute(k2_pv, cudaFuncAttributeMaxDynamicSharedMemorySize, K2_SMEM);

    const int nchunk = (int)((size_t)NB * SD * SD / 8);
    dim3 g1(16, NB), g2(8, NB);
    k1_qk<<<g1, 256, K1_SMEM>>>(Q, K);
    k_zred<<<NB, 512>>>();
    kvs<<<nchunk / 256, 256>>>(V);
    k2_pv<<<g2, 512, K2_SMEM>>>(out);
}

// round 13
// speedup vs baseline: 1.7548x; 1.7548x over previous
#include <cuda_runtime.h>
#include <cuda_bf16.h>
#include <cstdint>

#define SD 512
#define NB 512
#define SCALE 0.044194173824159216f

#define LDC 132        // fp32 staging stride (floats)
#define LDE1 80        // k1 byte stride: 32-bf16 rows (BK=32)
#define LDE 144        // k2 A byte stride: 64-bf16 rows
#define LDV 272        // k2 B byte stride (136 bf16)
#define K1_SMEM 67584  // A0/A1/A2 @0/10240/20480, B0/B1/B2 @30720/40960/51200; Cs aliases
#define K2_SMEM 107520 // A @0/18432/36864; B @55296/72704/90112

// ---- scratch (device globals; no allocation) ----
__device__ __align__(16) __nv_bfloat16 g_E[(size_t)NB * SD * SD];
__device__ __align__(16) __nv_bfloat16 g_Vh[(size_t)NB * SD * SD];
__device__ float g_partZ[NB][4][SD];
__device__ float g_Zinv[NB][SD];

__device__ __forceinline__ uint2 pack4(float4 v) {
    __nv_bfloat162 a = __float22bfloat162_rn(make_float2(v.x, v.y));
    __nv_bfloat162 b = __float22bfloat162_rn(make_float2(v.z, v.w));
    uint2 u; u.x = *(uint32_t*)&a; u.y = *(uint32_t*)&b; return u;
}
__device__ __forceinline__ uint4 pack8(float4 a, float4 b) {
    uint2 lo = pack4(a), hi = pack4(b);
    uint4 u; u.x = lo.x; u.y = lo.y; u.z = hi.x; u.w = hi.y; return u;
}
__device__ __forceinline__ uint32_t smem_u32(const void* p) {
    uint32_t a;
    asm("{ .reg .u64 t; cvta.to.shared.u64 t, %1; cvt.u32.u64 %0, t; }" : "=r"(a) : "l"(p));
    return a;
}
__device__ __forceinline__ void cpa16(uint32_t dst, const void* src) {
    asm volatile("cp.async.cg.shared.global [%0], [%1], 16;" :: "r"(dst), "l"(src));
}
#define CP_COMMIT() asm volatile("cp.async.commit_group;" ::: "memory")
#define CP_WAIT1()  asm volatile("cp.async.wait_group 1;" ::: "memory")
#define CP_WAIT0()  asm volatile("cp.async.wait_group 0;" ::: "memory")

__device__ __forceinline__ void ldsm4(uint32_t* r, uint32_t a) {
    asm volatile("ldmatrix.sync.aligned.m8n8.x4.shared.b16 {%0,%1,%2,%3}, [%4];"
                 : "=r"(r[0]), "=r"(r[1]), "=r"(r[2]), "=r"(r[3]) : "r"(a));
}
__device__ __forceinline__ void ldsm4t(uint32_t* r, uint32_t a) {
    asm volatile("ldmatrix.sync.aligned.m8n8.x4.trans.shared.b16 {%0,%1,%2,%3}, [%4];"
                 : "=r"(r[0]), "=r"(r[1]), "=r"(r[2]), "=r"(r[3]) : "r"(a));
}
__device__ __forceinline__ void mma16816(float* d, const uint32_t* a, const uint32_t* b) {
    asm volatile(
        "mma.sync.aligned.m16n8k16.row.col.f32.bf16.bf16.f32 "
        "{%0,%1,%2,%3},{%4,%5,%6,%7},{%8,%9},{%0,%1,%2,%3};"
        : "+f"(d[0]), "+f"(d[1]), "+f"(d[2]), "+f"(d[3])
        : "r"(a[0]), "r"(a[1]), "r"(a[2]), "r"(a[3]), "r"(b[0]), "r"(b[1]));
}

// ---------------------------------------------------------------------------
// k1: S = Q K^T (raw mma); register-prefetch + 3-stage smem, ONE bar/chunk.
// 256 thr, 8 warps (4x2), warp tile 32x64, BK=32. grid (16,512), 2 CTA/SM.
// ---------------------------------------------------------------------------
__global__ void __launch_bounds__(256, 2) k1_qk(const float* __restrict__ Q,
                                                const float* __restrict__ Km)
{
    extern __shared__ char sm[];
    const uint32_t sb = smem_u32(sm);
    __shared__ float zsh[256];

    const int batch = blockIdx.y, it = blockIdx.x >> 2, nt = blockIdx.x & 3;
    const float* Qb = Q  + ((size_t)batch * SD + it * 128) * SD;
    const float* Kb = Km + ((size_t)batch * SD + nt * 128) * SD;

    const int t = threadIdx.x, lane = t & 31, wid = t >> 5;
    const int R = (wid & 3) * 32, C = (wid >> 2) * 64;

    float d[2][8][4];
#pragma unroll
    for (int i = 0; i < 2; i++)
#pragma unroll
        for (int j = 0; j < 8; j++)
#pragma unroll
            for (int e = 0; e < 4; e++) d[i][j][e] = 0.0f;

    const int r0 = t >> 3, fc = (t & 7) * 4;
    const int aRow = (lane & 7) + ((lane >> 3) & 1) * 8;
    const uint32_t aK = ((lane >> 4) & 1) * 16;
    const uint32_t aBase = sb + (uint32_t)(R + aRow) * LDE1 + aK;
    const int bRow = (lane & 7) + ((lane >> 4) & 1) * 8;
    const uint32_t bK = ((lane >> 3) & 1) * 16;
    const uint32_t bBase = sb + 30720u + (uint32_t)(C + bRow) * LDE1 + bK;

    float4 pq[4], pk[4];   // prefetch registers

    auto ldgc = [&](int kk) {
#pragma unroll
        for (int p = 0; p < 4; p++) {
            const int row = r0 + p * 32;
            pq[p] = *(const float4*)(Qb + (size_t)row * SD + kk + fc);
            pk[p] = *(const float4*)(Kb + (size_t)row * SD + kk + fc);
        }
    };
    auto stsc = [&](int buf) {
#pragma unroll
        for (int p = 0; p < 4; p++) {
            const int row = r0 + p * 32;
            *(uint2*)(sm + buf * 10240 + row * LDE1 + fc * 2) = pack4(pq[p]);
            *(uint2*)(sm + 30720 + buf * 10240 + row * LDE1 + fc * 2) = pack4(pk[p]);
        }
    };

    // prologue: chunk0 -> buf0; prefetch chunk1 into regs
    ldgc(0);
    stsc(0);
    ldgc(32);
    __syncthreads();

    int bufc = 0;
#pragma unroll 1
    for (int c = 0; c < 16; c++) {
        const uint32_t aB = aBase + (uint32_t)bufc * 10240u;
        const uint32_t bB = bBase + (uint32_t)bufc * 10240u;
        uint32_t afr[2][4], bfr[4][4];
#pragma unroll
        for (int ks = 0; ks < 2; ks++) {
            const uint32_t ko = (uint32_t)ks * 32;
#pragma unroll
            for (int i = 0; i < 2; i++) ldsm4(afr[i], aB + i * 16 * LDE1 + ko);
#pragma unroll
            for (int j = 0; j < 4; j++) ldsm4(bfr[j], bB + j * 16 * LDE1 + ko);
#pragma unroll
            for (int i = 0; i < 2; i++)
#pragma unroll
                for (int j = 0; j < 4; j++) {
                    mma16816(d[i][2 * j],     afr[i], &bfr[j][0]);
                    mma16816(d[i][2 * j + 1], afr[i], &bfr[j][2]);
                }
        }
        const int bufn = (bufc == 2) ? 0 : bufc + 1;
        if (c < 15) stsc(bufn);          // chunk c+1 (regs landed during compute)
        if (c < 14) ldgc((c + 2) * 32);  // prefetch chunk c+2
        __syncthreads();                 // publish sts; fence WAR (2-iter window)
        bufc = bufn;
    }

    // exp in registers
#pragma unroll
    for (int i = 0; i < 2; i++)
#pragma unroll
        for (int j = 0; j < 8; j++)
#pragma unroll
            for (int e = 0; e < 4; e++)
                d[i][j][e] = __expf(d[i][j][e] * SCALE);

    // stage to fp32 smem (aliases tiles; final bar above fenced all reads)
    float* Cs = (float*)sm;
#pragma unroll
    for (int i = 0; i < 2; i++)
#pragma unroll
        for (int j = 0; j < 8; j++) {
            const int row = R + 16 * i + (lane >> 2);
            const int col = C + 8 * j + (lane & 3) * 2;
            *(float2*)&Cs[row * LDC + col] = make_float2(d[i][j][0], d[i][j][1]);
            *(float2*)&Cs[(row + 8) * LDC + col] = make_float2(d[i][j][2], d[i][j][3]);
        }
    __syncthreads();

    // deterministic column partial sums (2 threads/col, fixed order)
    {
        const int col = t & 127, half = t >> 7;
        float zsum = 0.f;
#pragma unroll 8
        for (int r = half * 64; r < half * 64 + 64; r++)
            zsum += Cs[r * LDC + col];
        zsh[half * 128 + col] = zsum;
        __syncthreads();
        if (t < 128)
            g_partZ[batch][it][nt * 128 + t] = zsh[t] + zsh[128 + t];
    }

    // coalesced bf16 E store
    __nv_bfloat16* Eb = g_E + ((size_t)batch * SD + it * 128) * SD + nt * 128;
    {
        const int row = t >> 1, c0 = (t & 1) * 64;
        const float* src = Cs + row * LDC + c0;
#pragma unroll
        for (int i = 0; i < 8; i++)
            *(uint4*)(Eb + (size_t)row * SD + c0 + i * 8) =
                pack8(*(const float4*)(src + i * 8), *(const float4*)(src + i * 8 + 4));
    }
}

// ---------------------------------------------------------------------------
__global__ void __launch_bounds__(512) k_zred()
{
    const int b = blockIdx.x, c = threadIdx.x;
    float z = g_partZ[b][0][c] + g_partZ[b][1][c] + g_partZ[b][2][c] + g_partZ[b][3][c];
    g_Zinv[b][c] = 1.0f / z;
}

// ---------------------------------------------------------------------------
__global__ void __launch_bounds__(256) kvs(const float* __restrict__ V)
{
    const int i = blockIdx.x * blockDim.x + threadIdx.x;
    const int b = i >> 15;
    const int k = (i & 32767) >> 6;
    const float zi = g_Zinv[b][k];
    const float4* src = (const float4*)(V + (size_t)i * 8);
    float4 a = src[0], c4 = src[1];
    a.x *= zi; a.y *= zi; a.z *= zi; a.w *= zi;
    c4.x *= zi; c4.y *= zi; c4.z *= zi; c4.w *= zi;
    *(uint4*)(g_Vh + (size_t)i * 8) = pack8(a, c4);
}

// ---------------------------------------------------------------------------
// k2: out = E @ V' — 3-stage cp.async pipeline, ONE bar/chunk, BK=64.
// 256 thr, 8 warps (4x2), warp tile 32x64. grid (16,512), 2 CTA/SM.
// smem: A @0/18432/36864 (128x144B); B @55296/72704/90112 (64x272B).
// ---------------------------------------------------------------------------
__global__ void __launch_bounds__(256, 2) k2_pv(float* __restrict__ O)
{
    extern __shared__ char sm[];
    const uint32_t sb = smem_u32(sm);

    const int batch = blockIdx.y, it = blockIdx.x >> 2, jt = blockIdx.x & 3;
    const char* Eblk = (const char*)(g_E + ((size_t)batch * SD + it * 128) * SD);
    const char* Vblk = (const char*)(g_Vh + (size_t)batch * SD * SD + jt * 128);

    const int t = threadIdx.x, lane = t & 31, wid = t >> 5;
    const int R = (wid & 3) * 32, C = (wid >> 2) * 64;

    const int ar = t >> 1, ac = t & 1;
    const int br = t >> 2, bc = t & 3;

    const int aRow = (lane & 7) + ((lane >> 3) & 1) * 8;
    const uint32_t aK = ((lane >> 4) & 1) * 16;
    const uint32_t aBase = sb + (uint32_t)(R + aRow) * LDE + aK;
    const int bKrow = lane & 15;
    const uint32_t bN = ((lane >> 4) & 1) * 16;
    const uint32_t bBase = sb + 55296u + (uint32_t)bKrow * LDV + (uint32_t)C * 2 + bN;

    float d[2][8][4];
#pragma unroll
    for (int i = 0; i < 2; i++)
#pragma unroll
        for (int j = 0; j < 8; j++)
#pragma unroll
            for (int e = 0; e < 4; e++) d[i][j][e] = 0.0f;

    auto issue = [&](int kk, int buf) {
        const uint32_t abuf = sb + buf * 18432;
        const uint32_t bbuf = sb + 55296 + buf * 17408;
#pragma unroll
        for (int q = 0; q < 4; q++)
            cpa16(abuf + (uint32_t)(ar * 144 + (ac * 4 + q) * 16),
                  Eblk + (size_t)ar * 1024 + (size_t)kk * 2 + (ac * 4 + q) * 16);
#pragma unroll
        for (int q = 0; q < 4; q++)
            cpa16(bbuf + (uint32_t)(br * 272 + (bc * 4 + q) * 16),
                  Vblk + (size_t)(kk + br) * 1024 + (bc * 4 + q) * 16);
        CP_COMMIT();
    };

    issue(0, 0);
    issue(64, 1);

    int bufc = 0;
#pragma unroll 1
    for (int c = 0; c < 8; c++) {
        if (c < 7) CP_WAIT1(); else CP_WAIT0();   // chunk c complete (own part)
        __syncthreads();                          // publish; fence buf (c+2)%3 WAR
        if (c < 6) {
            const int bufn2 = (bufc >= 1) ? bufc - 1 : bufc + 2;   // (c+2)%3
            issue((c + 2) * 64, bufn2);
        }
        const uint32_t aB = aBase + (uint32_t)bufc * 18432u;
        const uint32_t bB = bBase + (uint32_t)bufc * 17408u;

        uint32_t afr[2][2][4], bfr[2][4][4];
#pragma unroll
        for (int i = 0; i < 2; i++) ldsm4(afr[0][i], aB + i * 16 * LDE);
#pragma unroll
        for (int j = 0; j < 4; j++) ldsm4t(bfr[0][j], bB + j * 32);

#pragma unroll
        for (int ks = 0; ks < 4; ks++) {
            const int cur = ks & 1, nxt = cur ^ 1;
            if (ks < 3) {
                const uint32_t ao = (uint32_t)(ks + 1) * 32;
                const uint32_t bo = (uint32_t)(ks + 1) * (16 * LDV);
#pragma unroll
                for (int i = 0; i < 2; i++) ldsm4(afr[nxt][i], aB + i * 16 * LDE + ao);
#pragma unroll
                for (int j = 0; j < 4; j++) ldsm4t(bfr[nxt][j], bB + j * 32 + bo);
            }
#pragma unroll
            for (int i = 0; i < 2; i++)
#pragma unroll
                for (int j = 0; j < 4; j++) {
                    mma16816(d[i][2 * j],     afr[cur][i], &bfr[cur][j][0]);
                    mma16816(d[i][2 * j + 1], afr[cur][i], &bfr[cur][j][2]);
                }
        }
        bufc = (bufc == 2) ? 0 : bufc + 1;
    }

    float* Ob = O + ((size_t)batch * SD + it * 128) * SD + jt * 128;
#pragma unroll
    for (int i = 0; i < 2; i++)
#pragma unroll
        for (int j = 0; j < 8; j++) {
            const int row = R + 16 * i + (lane >> 2);
            const int col = C + 8 * j + (lane & 3) * 2;
            *(float2*)(Ob + (size_t)row * SD + col) = make_float2(d[i][j][0], d[i][j][1]);
            *(float2*)(Ob + (size_t)(row + 8) * SD + col) = make_float2(d[i][j][2], d[i][j][3]);
        }
}

// ---------------------------------------------------------------------------
extern "C" void kernel_launch(void* const* d_in, const int* in_sizes, int n_in,
                              void* d_out, int out_size)
{
    (void)in_sizes; (void)n_in; (void)out_size;
    const float* Q = (const float*)d_in[1];
    const float* K = (const float*)d_in[2];
    const float* V = (const float*)d_in[3];
    float* out = (float*)d_out;

    cudaFuncSetAttribute(k1_qk, cudaFuncAttributeMaxDynamicSharedMemorySize, K1_SMEM);
    cudaFuncSetAttribute(k2_pv, cudaFuncAttributeMaxDynamicSharedMemorySize, K2_SMEM);

    const int nchunk = (int)((size_t)NB * SD * SD / 8);
    dim3 g(16, NB);
    k1_qk<<<g, 256, K1_SMEM>>>(Q, K);
    k_zred<<<NB, 512>>>();
    kvs<<<nchunk / 256, 256>>>(V);
    k2_pv<<<g, 256, K2_SMEM>>>(out);
}